// round 2
// baseline (speedup 1.0000x reference)
#include <cuda_runtime.h>
#include <math.h>
#include <stdint.h>

#define NSn 100000
#define NMn 50000
#define En  600000
#define Dn  128
#define HORn 8
#define TINYF 1.17549435e-38f

// RNG derivation mode:
// 0: partitionable split = PRF pair at counter (0,j); 32-bit draws = o0^o1   (modern JAX default)
// 1: partitionable split via folded 32-bit bits at counters (0,2j),(0,2j+1)
// 2: original (non-partitionable) threefry counter layout
#ifndef RNG_MODE
#define RNG_MODE 0
#endif

// ---------------- scratch (device globals; no allocation allowed) ----------------
__device__ float    d_xl[(size_t)NSn * Dn];   // 51.2 MB
__device__ float    d_xr[(size_t)NMn * Dn];   // 25.6 MB
__device__ float    d_e[En];
__device__ float    d_ex[En];
__device__ unsigned d_mord[NMn];
__device__ float    d_s[NMn];
__device__ float    d_gsum[Dn];
__device__ float    d_gum[(size_t)HORn * NMn];
__device__ float    d_logits[NMn];
__device__ float    d_h[Dn], d_c[Dn], d_inp[Dn], d_hrelu[Dn];

// ---------------- threefry2x32 ----------------
__device__ __forceinline__ unsigned rotl32(unsigned x, int d) {
    return (x << d) | (x >> (32 - d));
}

__device__ __forceinline__ void tf2x32(unsigned k0, unsigned k1, unsigned c0, unsigned c1,
                                       unsigned& o0, unsigned& o1) {
    unsigned ks2 = k0 ^ k1 ^ 0x1BD11BDAu;
    unsigned x0 = c0 + k0, x1 = c1 + k1;
    const int ra[4] = {13, 15, 26, 6};
    const int rb[4] = {17, 29, 16, 24};
#pragma unroll
    for (int i = 0; i < 4; i++) { x0 += x1; x1 = rotl32(x1, ra[i]); x1 ^= x0; }
    x0 += k1; x1 += ks2 + 1u;
#pragma unroll
    for (int i = 0; i < 4; i++) { x0 += x1; x1 = rotl32(x1, rb[i]); x1 ^= x0; }
    x0 += ks2; x1 += k0 + 2u;
#pragma unroll
    for (int i = 0; i < 4; i++) { x0 += x1; x1 = rotl32(x1, ra[i]); x1 ^= x0; }
    x0 += k0; x1 += k1 + 3u;
#pragma unroll
    for (int i = 0; i < 4; i++) { x0 += x1; x1 = rotl32(x1, rb[i]); x1 ^= x0; }
    x0 += k1; x1 += ks2 + 4u;
#pragma unroll
    for (int i = 0; i < 4; i++) { x0 += x1; x1 = rotl32(x1, ra[i]); x1 ^= x0; }
    x0 += ks2; x1 += k0 + 5u;
    o0 = x0; o1 = x1;
}

// ---------------- gumbel noise (bit-exact JAX semantics) ----------------
__global__ void gumbel_kernel() {
    int idx = blockIdx.x * blockDim.x + threadIdx.x;
    if (idx >= HORn * NMn) return;
    int step = idx / NMn;
    int i = idx - step * NMn;

    unsigned k0, k1;
#if RNG_MODE == 0
    tf2x32(0u, 42u, 0u, (unsigned)step, k0, k1);
#elif RNG_MODE == 1
    { unsigned a0, a1, b0, b1;
      tf2x32(0u, 42u, 0u, (unsigned)(2 * step), a0, a1);     k0 = a0 ^ a1;
      tf2x32(0u, 42u, 0u, (unsigned)(2 * step + 1), b0, b1); k1 = b0 ^ b1; }
#else
    // original split: counts=iota(16); x0=0..7 pairs with x1=8..15; out=concat(o0s,o1s)
    { unsigned t0 = (unsigned)(2 * step), t1 = (unsigned)(2 * step + 1);
      unsigned p0, p1, q0, q1;
      if (t0 < 8) { tf2x32(0u, 42u, t0, t0 + 8u, p0, p1); k0 = p0; }
      else        { tf2x32(0u, 42u, t0 - 8u, t0, p0, p1); k0 = p1; }
      if (t1 < 8) { tf2x32(0u, 42u, t1, t1 + 8u, q0, q1); k1 = q0; }
      else        { tf2x32(0u, 42u, t1 - 8u, t1, q0, q1); k1 = q1; } }
#endif

    unsigned bits;
#if RNG_MODE == 2
    { unsigned c = (i < NMn / 2) ? (unsigned)i : (unsigned)(i - NMn / 2);
      unsigned o0, o1;
      tf2x32(k0, k1, c, c + (unsigned)(NMn / 2), o0, o1);
      bits = (i < NMn / 2) ? o0 : o1; }
#else
    { unsigned o0, o1;
      tf2x32(k0, k1, 0u, (unsigned)i, o0, o1);
      bits = o0 ^ o1; }
#endif

    float u = __uint_as_float((bits >> 9) | 0x3f800000u) - 1.0f;
    u = u + TINYF;                 // u*(1 - tiny) folds to u*1.0 in f32
    u = fmaxf(TINYF, u);
    d_gum[idx] = -logf(-logf(u));
}

// ---------------- float ordered-int helpers for atomicMax ----------------
__device__ __forceinline__ unsigned ford(float f) {
    unsigned u = __float_as_uint(f);
    return (u & 0x80000000u) ? ~u : (u | 0x80000000u);
}
__device__ __forceinline__ float ford_dec(unsigned v) {
    unsigned u = (v & 0x80000000u) ? (v & 0x7fffffffu) : ~v;
    return __uint_as_float(u);
}

// ---------------- init ----------------
__global__ void init_kernel() {
    int i = blockIdx.x * blockDim.x + threadIdx.x;
    if (i < NMn) { d_mord[i] = 0u; d_s[i] = 0.0f; }
    if (i < Dn) d_gsum[i] = 0.0f;
}

// ---------------- GEMM: C[N,128] = A[N,128] * W[128,128]^T ----------------
__global__ __launch_bounds__(256) void gemm_xwt(const float* __restrict__ A,
                                                const float* __restrict__ W,
                                                float* __restrict__ C, int N) {
    __shared__ float As[16][64];
    __shared__ float Ws[16][128];
    int tid = threadIdx.x;
    int tn = tid & 31, tm = tid >> 5;
    int rowBase = blockIdx.x * 64;

    float acc[8][4];
#pragma unroll
    for (int i = 0; i < 8; i++)
#pragma unroll
        for (int j = 0; j < 4; j++) acc[i][j] = 0.0f;

    int lr = tid >> 2;          // 0..63
    int lk = (tid & 3) * 4;     // 0,4,8,12
    int ar = rowBase + lr; if (ar >= N) ar = N - 1;

    for (int k0 = 0; k0 < Dn; k0 += 16) {
        float4 av = *(const float4*)(A + (size_t)ar * Dn + k0 + lk);
        As[lk + 0][lr] = av.x; As[lk + 1][lr] = av.y;
        As[lk + 2][lr] = av.z; As[lk + 3][lr] = av.w;
#pragma unroll
        for (int r = 0; r < 2; r++) {
            int q = tid + 256 * r;          // 0..511
            int col = q >> 2; int kq = (q & 3) * 4;
            float4 wv = *(const float4*)(W + (size_t)col * Dn + k0 + kq);
            Ws[kq + 0][col] = wv.x; Ws[kq + 1][col] = wv.y;
            Ws[kq + 2][col] = wv.z; Ws[kq + 3][col] = wv.w;
        }
        __syncthreads();
#pragma unroll
        for (int kk = 0; kk < 16; kk++) {
            float4 b = *(const float4*)&Ws[kk][tn * 4];
#pragma unroll
            for (int i = 0; i < 8; i++) {
                float a = As[kk][tm * 8 + i];
                acc[i][0] += a * b.x; acc[i][1] += a * b.y;
                acc[i][2] += a * b.z; acc[i][3] += a * b.w;
            }
        }
        __syncthreads();
    }
#pragma unroll
    for (int i = 0; i < 8; i++) {
        int r = rowBase + tm * 8 + i;
        if (r < N)
            *(float4*)(C + (size_t)r * Dn + tn * 4) =
                make_float4(acc[i][0], acc[i][1], acc[i][2], acc[i][3]);
    }
}

// ---------------- GAT edge phase 1: e = att . leakyrelu(xl[src]+xr[dst]); seg-max ----------------
__global__ void edge_score_kernel(const int* __restrict__ ei,
                                  const float* __restrict__ att) {
    int lane = threadIdx.x & 31;
    int warp = (blockIdx.x * blockDim.x + threadIdx.x) >> 5;
    int nwarps = (gridDim.x * blockDim.x) >> 5;
    float4 a4 = ((const float4*)att)[lane];
    for (int e = warp; e < En; e += nwarps) {
        int s = ei[e];
        int d = ei[En + e];
        float4 xl = ((const float4*)(d_xl + (size_t)s * Dn))[lane];
        float4 xr = ((const float4*)(d_xr + (size_t)d * Dn))[lane];
        float z0 = xl.x + xr.x, z1 = xl.y + xr.y, z2 = xl.z + xr.z, z3 = xl.w + xr.w;
        z0 = (z0 > 0.0f) ? z0 : 0.2f * z0;
        z1 = (z1 > 0.0f) ? z1 : 0.2f * z1;
        z2 = (z2 > 0.0f) ? z2 : 0.2f * z2;
        z3 = (z3 > 0.0f) ? z3 : 0.2f * z3;
        float p = z0 * a4.x + z1 * a4.y + z2 * a4.z + z3 * a4.w;
#pragma unroll
        for (int o = 16; o; o >>= 1) p += __shfl_xor_sync(0xffffffffu, p, o);
        if (lane == 0) {
            d_e[e] = p;
            atomicMax(&d_mord[d], ford(p));
        }
    }
}

// ---------------- GAT edge phase 2: ex = exp(e - m[dst]); seg-sum ----------------
__global__ void edge_exp_kernel(const int* __restrict__ ei) {
    int e = blockIdx.x * blockDim.x + threadIdx.x;
    if (e >= En) return;
    int d = ei[En + e];
    float m = ford_dec(d_mord[d]);
    float ex = expf(d_e[e] - m);
    d_ex[e] = ex;
    atomicAdd(&d_s[d], ex);
}

// ---------------- GAT edge phase 3: gsum += alpha * xl[src] ----------------
__global__ void edge_accum_kernel(const int* __restrict__ ei) {
    __shared__ float sacc[8][Dn];
    int lane = threadIdx.x & 31;
    int wib = threadIdx.x >> 5;  // warp in block (0..7)
    int warp = (blockIdx.x * blockDim.x + threadIdx.x) >> 5;
    int nwarps = (gridDim.x * blockDim.x) >> 5;
    float4 acc = make_float4(0.f, 0.f, 0.f, 0.f);
    for (int e = warp; e < En; e += nwarps) {
        int s = ei[e];
        int d = ei[En + e];
        float alpha = d_ex[e] / d_s[d];
        float4 xl = ((const float4*)(d_xl + (size_t)s * Dn))[lane];
        acc.x += alpha * xl.x; acc.y += alpha * xl.y;
        acc.z += alpha * xl.z; acc.w += alpha * xl.w;
    }
    sacc[wib][lane * 4 + 0] = acc.x;
    sacc[wib][lane * 4 + 1] = acc.y;
    sacc[wib][lane * 4 + 2] = acc.z;
    sacc[wib][lane * 4 + 3] = acc.w;
    __syncthreads();
    int t = threadIdx.x;
    if (t < Dn) {
        float v = 0.0f;
#pragma unroll
        for (int w = 0; w < 8; w++) v += sacc[w][t];
        atomicAdd(&d_gsum[t], v);
    }
}

// ---------------- finalize g, reset LSTM state ----------------
__global__ void finalize_g_kernel(const float* __restrict__ conv_bias) {
    int t = threadIdx.x;
    if (t < Dn) {
        d_inp[t] = d_gsum[t] * (1.0f / (float)NMn) + conv_bias[t];
        d_h[t] = 0.0f;
        d_c[t] = 0.0f;
    }
}

// ---------------- LSTM cell + first MLP layer (one block, 512 threads) ----------------
__device__ __forceinline__ float sigm(float x) { return 1.0f / (1.0f + expf(-x)); }

__global__ __launch_bounds__(512) void lstm_kernel(const float* __restrict__ Wih,
                                                   const float* __restrict__ Whh,
                                                   const float* __restrict__ bih,
                                                   const float* __restrict__ bhh,
                                                   const float* __restrict__ W1,
                                                   const float* __restrict__ b1) {
    __shared__ float s_inp[Dn], s_h[Dn], s_gates[4 * Dn];
    int t = threadIdx.x;
    if (t < Dn) { s_inp[t] = d_inp[t]; s_h[t] = d_h[t]; }
    __syncthreads();
    {
        float a = bih[t] + bhh[t];
        const float4* wi = (const float4*)(Wih + (size_t)t * Dn);
        const float4* wh = (const float4*)(Whh + (size_t)t * Dn);
#pragma unroll 8
        for (int k = 0; k < Dn / 4; k++) {
            float4 w4 = wi[k];
            a += w4.x * s_inp[4 * k] + w4.y * s_inp[4 * k + 1] +
                 w4.z * s_inp[4 * k + 2] + w4.w * s_inp[4 * k + 3];
            float4 v4 = wh[k];
            a += v4.x * s_h[4 * k] + v4.y * s_h[4 * k + 1] +
                 v4.z * s_h[4 * k + 2] + v4.w * s_h[4 * k + 3];
        }
        s_gates[t] = a;
    }
    __syncthreads();
    if (t < Dn) {
        float ig = sigm(s_gates[t]);
        float fg = sigm(s_gates[Dn + t]);
        float gg = tanhf(s_gates[2 * Dn + t]);
        float og = sigm(s_gates[3 * Dn + t]);
        float c = fg * d_c[t] + ig * gg;
        float h = og * tanhf(c);
        d_c[t] = c; d_h[t] = h; s_h[t] = h;
    }
    __syncthreads();
    if (t < Dn) {
        float a = b1[t];
        const float4* w = (const float4*)(W1 + (size_t)t * Dn);
#pragma unroll 8
        for (int k = 0; k < Dn / 4; k++) {
            float4 w4 = w[k];
            a += w4.x * s_h[4 * k] + w4.y * s_h[4 * k + 1] +
                 w4.z * s_h[4 * k + 2] + w4.w * s_h[4 * k + 3];
        }
        d_hrelu[t] = fmaxf(a, 0.0f);
    }
}

// ---------------- logits = hrelu @ W2^T + b2 ----------------
__global__ void logits_kernel(const float* __restrict__ W2, const float* __restrict__ b2) {
    int lane = threadIdx.x & 31;
    int warp = (blockIdx.x * blockDim.x + threadIdx.x) >> 5;
    int nwarps = (gridDim.x * blockDim.x) >> 5;
    float4 h4 = ((const float4*)d_hrelu)[lane];
    for (int j = warp; j < NMn; j += nwarps) {
        float4 w = ((const float4*)(W2 + (size_t)j * Dn))[lane];
        float p = w.x * h4.x + w.y * h4.y + w.z * h4.z + w.w * h4.w;
#pragma unroll
        for (int o = 16; o; o >>= 1) p += __shfl_xor_sync(0xffffffffu, p, o);
        if (lane == 0) d_logits[j] = p + b2[j];
    }
}

// ---------------- sample: argmax(logits+gumbel), logsumexp, feed emb[action] ----------------
__global__ __launch_bounds__(256) void sample_kernel(int step, const float* __restrict__ emb,
                                                     float* __restrict__ out, int out_size) {
    __shared__ float sM[256], sS[256], sBv[256];
    __shared__ int sBi[256];
    __shared__ int s_act;
    int t = threadIdx.x;
    float M = -INFINITY, S = 0.0f, bv = -INFINITY;
    int bi = 0;
    const float* gum = d_gum + (size_t)step * NMn;
    for (int j = t; j < NMn; j += 256) {
        float l = d_logits[j];
        if (l > M) { S = S * expf(M - l) + 1.0f; M = l; }
        else       { S += expf(l - M); }
        float v = l + gum[j];
        if (v > bv) { bv = v; bi = j; }
    }
    sM[t] = M; sS[t] = S; sBv[t] = bv; sBi[t] = bi;
    __syncthreads();
    for (int o = 128; o; o >>= 1) {
        if (t < o) {
            float M2 = sM[t + o], S2 = sS[t + o];
            if (M2 > sM[t]) { sS[t] = sS[t] * expf(sM[t] - M2) + S2; sM[t] = M2; }
            else            { sS[t] += S2 * expf(M2 - sM[t]); }
            if (sBv[t + o] > sBv[t] || (sBv[t + o] == sBv[t] && sBi[t + o] < sBi[t])) {
                sBv[t] = sBv[t + o]; sBi[t] = sBi[t + o];
            }
        }
        __syncthreads();
    }
    if (t == 0) {
        int act = sBi[0];
        s_act = act;
        if (step < out_size) out[step] = (float)act;
        if (8 + step < out_size) out[8 + step] = d_logits[act] - (sM[0] + logf(sS[0]));
    }
    __syncthreads();
    if (t < Dn) d_inp[t] = emb[(size_t)s_act * Dn + t];
}

// ---------------- final h, c ----------------
__global__ void write_hc_kernel(float* __restrict__ out, int out_size) {
    int t = threadIdx.x;
    if (t < Dn) {
        if (16 + t < out_size) out[16 + t] = d_h[t];
        if (144 + t < out_size) out[144 + t] = d_c[t];
    }
}

// ---------------- host launcher ----------------
extern "C" void kernel_launch(void* const* d_in, const int* in_sizes, int n_in,
                              void* d_out, int out_size) {
    const float* state = (const float*)d_in[0];
    const float* model = (const float*)d_in[1];
    const int*   ei    = (const int*)d_in[2];
    const float* W_l   = (const float*)d_in[3];
    const float* W_r   = (const float*)d_in[4];
    const float* att   = (const float*)d_in[5];
    const float* cbias = (const float*)d_in[6];
    const float* Wih   = (const float*)d_in[7];
    const float* Whh   = (const float*)d_in[8];
    const float* bih   = (const float*)d_in[9];
    const float* bhh   = (const float*)d_in[10];
    const float* pW1   = (const float*)d_in[11];
    const float* pb1   = (const float*)d_in[12];
    const float* pW2   = (const float*)d_in[13];
    const float* pb2   = (const float*)d_in[14];
    const float* emb   = (const float*)d_in[15];
    float* out = (float*)d_out;

    float* xl_ptr = nullptr;
    float* xr_ptr = nullptr;
    cudaGetSymbolAddress((void**)&xl_ptr, d_xl);
    cudaGetSymbolAddress((void**)&xr_ptr, d_xr);

    gumbel_kernel<<<(HORn * NMn + 255) / 256, 256>>>();
    init_kernel<<<(NMn + 255) / 256, 256>>>();

    gemm_xwt<<<(NSn + 63) / 64, 256>>>(state, W_l, xl_ptr, NSn);
    gemm_xwt<<<(NMn + 63) / 64, 256>>>(model, W_r, xr_ptr, NMn);

    edge_score_kernel<<<1024, 256>>>(ei, att);
    edge_exp_kernel<<<(En + 255) / 256, 256>>>(ei);
    edge_accum_kernel<<<1024, 256>>>(ei);

    finalize_g_kernel<<<1, 128>>>(cbias);

    for (int step = 0; step < HORn; step++) {
        lstm_kernel<<<1, 512>>>(Wih, Whh, bih, bhh, pW1, pb1);
        logits_kernel<<<512, 256>>>(pW2, pb2);
        sample_kernel<<<1, 256>>>(step, emb, out, out_size);
    }
    write_hc_kernel<<<1, 128>>>(out, out_size);
}

// round 3
// speedup vs baseline: 1.4224x; 1.4224x over previous
#include <cuda_runtime.h>
#include <math.h>
#include <stdint.h>

#define NSn 100000
#define NMn 50000
#define En  600000
#define Dn  128
#define HORn 8
#define NB  148          // persistent-kernel blocks (<= SM count, all co-resident)
#define TINYF 1.17549435e-38f

#ifndef RNG_MODE
#define RNG_MODE 0
#endif

// ---------------- scratch (device globals; no allocation allowed) ----------------
__device__ float    d_xl[(size_t)NSn * Dn];   // 51.2 MB
__device__ float    d_xr[(size_t)NMn * Dn];   // 25.6 MB
__device__ float    d_e[En];
__device__ unsigned d_mord[NMn];
__device__ float    d_s[NMn];
__device__ float    d_w[NSn];                 // per-source attention mass
__device__ float    d_v[Dn];                  // sum_s w_s * state[s]
__device__ float    d_gum[(size_t)HORn * NMn];
__device__ float    d_hrelu[Dn];
__device__ float    d_pM[NB], d_pS[NB];       // per-block logsumexp partials
__device__ unsigned long long d_amax;         // packed argmax (ford(v)<<32 | ~idx)
__device__ unsigned d_bar_cnt;                // grid barrier counter (reset each replay)

// ---------------- threefry2x32 ----------------
__device__ __forceinline__ unsigned rotl32(unsigned x, int d) {
    return (x << d) | (x >> (32 - d));
}

__device__ __forceinline__ void tf2x32(unsigned k0, unsigned k1, unsigned c0, unsigned c1,
                                       unsigned& o0, unsigned& o1) {
    unsigned ks2 = k0 ^ k1 ^ 0x1BD11BDAu;
    unsigned x0 = c0 + k0, x1 = c1 + k1;
    const int ra[4] = {13, 15, 26, 6};
    const int rb[4] = {17, 29, 16, 24};
#pragma unroll
    for (int i = 0; i < 4; i++) { x0 += x1; x1 = rotl32(x1, ra[i]); x1 ^= x0; }
    x0 += k1; x1 += ks2 + 1u;
#pragma unroll
    for (int i = 0; i < 4; i++) { x0 += x1; x1 = rotl32(x1, rb[i]); x1 ^= x0; }
    x0 += ks2; x1 += k0 + 2u;
#pragma unroll
    for (int i = 0; i < 4; i++) { x0 += x1; x1 = rotl32(x1, ra[i]); x1 ^= x0; }
    x0 += k0; x1 += k1 + 3u;
#pragma unroll
    for (int i = 0; i < 4; i++) { x0 += x1; x1 = rotl32(x1, rb[i]); x1 ^= x0; }
    x0 += k1; x1 += ks2 + 4u;
#pragma unroll
    for (int i = 0; i < 4; i++) { x0 += x1; x1 = rotl32(x1, ra[i]); x1 ^= x0; }
    x0 += ks2; x1 += k0 + 5u;
    o0 = x0; o1 = x1;
}

// ---------------- gumbel noise (bit-exact JAX semantics) ----------------
__global__ void gumbel_kernel() {
    int idx = blockIdx.x * blockDim.x + threadIdx.x;
    if (idx >= HORn * NMn) return;
    int step = idx / NMn;
    int i = idx - step * NMn;

    unsigned k0, k1;
#if RNG_MODE == 0
    tf2x32(0u, 42u, 0u, (unsigned)step, k0, k1);
#elif RNG_MODE == 1
    { unsigned a0, a1, b0, b1;
      tf2x32(0u, 42u, 0u, (unsigned)(2 * step), a0, a1);     k0 = a0 ^ a1;
      tf2x32(0u, 42u, 0u, (unsigned)(2 * step + 1), b0, b1); k1 = b0 ^ b1; }
#else
    { unsigned t0 = (unsigned)(2 * step), t1 = (unsigned)(2 * step + 1);
      unsigned p0, p1, q0, q1;
      if (t0 < 8) { tf2x32(0u, 42u, t0, t0 + 8u, p0, p1); k0 = p0; }
      else        { tf2x32(0u, 42u, t0 - 8u, t0, p0, p1); k0 = p1; }
      if (t1 < 8) { tf2x32(0u, 42u, t1, t1 + 8u, q0, q1); k1 = q0; }
      else        { tf2x32(0u, 42u, t1 - 8u, t1, q0, q1); k1 = q1; } }
#endif

    unsigned bits;
#if RNG_MODE == 2
    { unsigned c = (i < NMn / 2) ? (unsigned)i : (unsigned)(i - NMn / 2);
      unsigned o0, o1;
      tf2x32(k0, k1, c, c + (unsigned)(NMn / 2), o0, o1);
      bits = (i < NMn / 2) ? o0 : o1; }
#else
    { unsigned o0, o1;
      tf2x32(k0, k1, 0u, (unsigned)i, o0, o1);
      bits = o0 ^ o1; }
#endif

    float u = __uint_as_float((bits >> 9) | 0x3f800000u) - 1.0f;
    u = u + TINYF;
    u = fmaxf(TINYF, u);
    d_gum[idx] = -logf(-logf(u));
}

// ---------------- float ordered-int helpers ----------------
__device__ __forceinline__ unsigned ford(float f) {
    unsigned u = __float_as_uint(f);
    return (u & 0x80000000u) ? ~u : (u | 0x80000000u);
}
__device__ __forceinline__ float ford_dec(unsigned v) {
    unsigned u = (v & 0x80000000u) ? (v & 0x7fffffffu) : ~v;
    return __uint_as_float(u);
}

// ---------------- init (also resets persistent-kernel barrier state) ----------------
__global__ void init_kernel() {
    int i = blockIdx.x * blockDim.x + threadIdx.x;
    if (i < NMn) { d_mord[i] = 0u; d_s[i] = 0.0f; }
    if (i < NSn) d_w[i] = 0.0f;
    if (i < Dn) d_v[i] = 0.0f;
    if (i == 0) { d_amax = 0ull; d_bar_cnt = 0u; }
}

// ---------------- GEMM: C[N,128] = A[N,128] * W[128,128]^T ----------------
__global__ __launch_bounds__(256) void gemm_xwt(const float* __restrict__ A,
                                                const float* __restrict__ W,
                                                float* __restrict__ C, int N) {
    __shared__ float As[16][64];
    __shared__ float Ws[16][128];
    int tid = threadIdx.x;
    int tn = tid & 31, tm = tid >> 5;
    int rowBase = blockIdx.x * 64;

    float acc[8][4];
#pragma unroll
    for (int i = 0; i < 8; i++)
#pragma unroll
        for (int j = 0; j < 4; j++) acc[i][j] = 0.0f;

    int lr = tid >> 2;
    int lk = (tid & 3) * 4;
    int ar = rowBase + lr; if (ar >= N) ar = N - 1;

    for (int k0 = 0; k0 < Dn; k0 += 16) {
        float4 av = *(const float4*)(A + (size_t)ar * Dn + k0 + lk);
        As[lk + 0][lr] = av.x; As[lk + 1][lr] = av.y;
        As[lk + 2][lr] = av.z; As[lk + 3][lr] = av.w;
#pragma unroll
        for (int r = 0; r < 2; r++) {
            int q = tid + 256 * r;
            int col = q >> 2; int kq = (q & 3) * 4;
            float4 wv = *(const float4*)(W + (size_t)col * Dn + k0 + kq);
            Ws[kq + 0][col] = wv.x; Ws[kq + 1][col] = wv.y;
            Ws[kq + 2][col] = wv.z; Ws[kq + 3][col] = wv.w;
        }
        __syncthreads();
#pragma unroll
        for (int kk = 0; kk < 16; kk++) {
            float4 b = *(const float4*)&Ws[kk][tn * 4];
#pragma unroll
            for (int i = 0; i < 8; i++) {
                float a = As[kk][tm * 8 + i];
                acc[i][0] += a * b.x; acc[i][1] += a * b.y;
                acc[i][2] += a * b.z; acc[i][3] += a * b.w;
            }
        }
        __syncthreads();
    }
#pragma unroll
    for (int i = 0; i < 8; i++) {
        int r = rowBase + tm * 8 + i;
        if (r < N)
            *(float4*)(C + (size_t)r * Dn + tn * 4) =
                make_float4(acc[i][0], acc[i][1], acc[i][2], acc[i][3]);
    }
}

// ---------------- GAT edge phase 1: e = att . leakyrelu(xl[src]+xr[dst]); seg-max ----------------
__global__ void edge_score_kernel(const int* __restrict__ ei,
                                  const float* __restrict__ att) {
    int lane = threadIdx.x & 31;
    int warp = (blockIdx.x * blockDim.x + threadIdx.x) >> 5;
    int nwarps = (gridDim.x * blockDim.x) >> 5;
    float4 a4 = ((const float4*)att)[lane];
    for (int e = warp; e < En; e += nwarps) {
        int s = ei[e];
        int d = ei[En + e];
        float4 xl = ((const float4*)(d_xl + (size_t)s * Dn))[lane];
        float4 xr = ((const float4*)(d_xr + (size_t)d * Dn))[lane];
        float z0 = xl.x + xr.x, z1 = xl.y + xr.y, z2 = xl.z + xr.z, z3 = xl.w + xr.w;
        z0 = (z0 > 0.0f) ? z0 : 0.2f * z0;
        z1 = (z1 > 0.0f) ? z1 : 0.2f * z1;
        z2 = (z2 > 0.0f) ? z2 : 0.2f * z2;
        z3 = (z3 > 0.0f) ? z3 : 0.2f * z3;
        float p = z0 * a4.x + z1 * a4.y + z2 * a4.z + z3 * a4.w;
#pragma unroll
        for (int o = 16; o; o >>= 1) p += __shfl_xor_sync(0xffffffffu, p, o);
        if (lane == 0) {
            d_e[e] = p;
            atomicMax(&d_mord[d], ford(p));
        }
    }
}

// ---------------- edge phase 2: s[d] += exp(e - m[d]) ----------------
__global__ void edge_exp_kernel(const int* __restrict__ ei) {
    int e = blockIdx.x * blockDim.x + threadIdx.x;
    if (e >= En) return;
    int d = ei[En + e];
    float m = ford_dec(d_mord[d]);
    atomicAdd(&d_s[d], expf(d_e[e] - m));
}

// ---------------- edge phase 3: w[src] += exp(e - m[d]) / s[d] ----------------
__global__ void edge_w_kernel(const int* __restrict__ ei) {
    int e = blockIdx.x * blockDim.x + threadIdx.x;
    if (e >= En) return;
    int s = ei[e];
    int d = ei[En + e];
    float m = ford_dec(d_mord[d]);
    atomicAdd(&d_w[s], expf(d_e[e] - m) / d_s[d]);
}

// ---------------- persistent fused policy kernel ----------------
__device__ __forceinline__ float sigm(float x) { return 1.0f / (1.0f + expf(-x)); }

__device__ __forceinline__ void grid_sync(unsigned target) {
    __syncthreads();
    if (threadIdx.x == 0) {
        __threadfence();
        atomicAdd(&d_bar_cnt, 1u);
        while (*((volatile unsigned*)&d_bar_cnt) < target) { }
        __threadfence();
    }
    __syncthreads();
}

__global__ __launch_bounds__(256) void policy_kernel(
    const float* __restrict__ state,
    const float* __restrict__ W_l,
    const float* __restrict__ cbias,
    const float* __restrict__ Wih, const float* __restrict__ Whh,
    const float* __restrict__ bih, const float* __restrict__ bhh,
    const float* __restrict__ W1,  const float* __restrict__ b1,
    const float* __restrict__ W2,  const float* __restrict__ b2,
    const float* __restrict__ emb,
    float* __restrict__ out, int out_size)
{
    __shared__ float s_inp[Dn], s_h[Dn], s_c[Dn], s_hrelu[Dn];
    __shared__ float s_gates[4 * Dn];
    __shared__ float s_red[8 * Dn];
    __shared__ float s_wM[8], s_wS[8], s_wBv[8];
    __shared__ int   s_wBi[8];
    __shared__ float s_rM[160], s_rS[160];
    __shared__ int   s_act;
    __shared__ float s_Mg, s_logit;

    const int t = threadIdx.x;
    const int lane = t & 31;
    const int wib = t >> 5;
    const int b = blockIdx.x;
    unsigned bar = 0;

    // ---- prologue: v = sum_s w_s * state[s] (all blocks) ----
    {
        int gw = b * 8 + wib;
        float4 acc = make_float4(0.f, 0.f, 0.f, 0.f);
        for (int s = gw; s < NSn; s += NB * 8) {
            float ws = d_w[s];
            if (ws != 0.0f) {
                float4 x = ((const float4*)(state + (size_t)s * Dn))[lane];
                acc.x += ws * x.x; acc.y += ws * x.y;
                acc.z += ws * x.z; acc.w += ws * x.w;
            }
        }
        s_red[wib * Dn + lane * 4 + 0] = acc.x;
        s_red[wib * Dn + lane * 4 + 1] = acc.y;
        s_red[wib * Dn + lane * 4 + 2] = acc.z;
        s_red[wib * Dn + lane * 4 + 3] = acc.w;
        __syncthreads();
        if (t < Dn) {
            float v = 0.0f;
#pragma unroll
            for (int w = 0; w < 8; w++) v += s_red[w * Dn + t];
            atomicAdd(&d_v[t], v);
        }
    }
    bar += NB; grid_sync(bar);

    // ---- block 0: g = (W_l @ v)/NM + cbias ; h=c=0 ----
    if (b == 0) {
        if (t < Dn) { s_red[t] = d_v[t]; s_h[t] = 0.0f; s_c[t] = 0.0f; }
        __syncthreads();
        if (t < Dn) {
            float a = 0.0f;
            const float4* wr = (const float4*)(W_l + (size_t)t * Dn);
            const float4* vv = (const float4*)s_red;
#pragma unroll 8
            for (int k = 0; k < Dn / 4; k++) {
                float4 w4 = wr[k]; float4 v4 = vv[k];
                a += w4.x * v4.x + w4.y * v4.y + w4.z * v4.z + w4.w * v4.w;
            }
            s_inp[t] = a * (1.0f / (float)NMn) + cbias[t];
        }
        __syncthreads();
    }

    const int chunk = (NMn + NB - 1) / NB;       // 338
    const int row0 = b * chunk;
    const int row1 = (row0 + chunk < NMn) ? (row0 + chunk) : NMn;

    for (int step = 0; step < HORn; step++) {
        // ---- phase A: LSTM + MLP1 (block 0 only) ----
        if (b == 0) {
#pragma unroll
            for (int rr = 0; rr < 2; rr++) {
                int r = t + rr * 256;
                float a = bih[r] + bhh[r];
                const float4* wi = (const float4*)(Wih + (size_t)r * Dn);
                const float4* wh = (const float4*)(Whh + (size_t)r * Dn);
                const float4* pi = (const float4*)s_inp;
                const float4* ph = (const float4*)s_h;
#pragma unroll 8
                for (int k = 0; k < Dn / 4; k++) {
                    float4 w4 = wi[k]; float4 i4 = pi[k];
                    a += w4.x * i4.x + w4.y * i4.y + w4.z * i4.z + w4.w * i4.w;
                    float4 v4 = wh[k]; float4 h4 = ph[k];
                    a += v4.x * h4.x + v4.y * h4.y + v4.z * h4.z + v4.w * h4.w;
                }
                s_gates[r] = a;
            }
            __syncthreads();
            if (t < Dn) {
                float ig = sigm(s_gates[t]);
                float fg = sigm(s_gates[Dn + t]);
                float gg = tanhf(s_gates[2 * Dn + t]);
                float og = sigm(s_gates[3 * Dn + t]);
                float c = fg * s_c[t] + ig * gg;
                float h = og * tanhf(c);
                s_c[t] = c; s_h[t] = h;
            }
            __syncthreads();
            if (t < Dn) {
                float a = b1[t];
                const float4* wr = (const float4*)(W1 + (size_t)t * Dn);
                const float4* ph = (const float4*)s_h;
#pragma unroll 8
                for (int k = 0; k < Dn / 4; k++) {
                    float4 w4 = wr[k]; float4 h4 = ph[k];
                    a += w4.x * h4.x + w4.y * h4.y + w4.z * h4.z + w4.w * h4.w;
                }
                float hr = fmaxf(a, 0.0f);
                d_hrelu[t] = hr;
            }
        }
        bar += NB; grid_sync(bar);

        // ---- phase B: logits chunk + partial logsumexp + argmax (all blocks) ----
        if (t < Dn) s_hrelu[t] = d_hrelu[t];
        __syncthreads();
        {
            float4 h4 = ((const float4*)s_hrelu)[lane];
            const float* gum = d_gum + (size_t)step * NMn;
            float M = -INFINITY, S = 0.0f, bv = -INFINITY;
            int bi = 0;
            for (int j = row0 + wib; j < row1; j += 8) {
                float4 w4 = ((const float4*)(W2 + (size_t)j * Dn))[lane];
                float p = w4.x * h4.x + w4.y * h4.y + w4.z * h4.z + w4.w * h4.w;
#pragma unroll
                for (int o = 16; o; o >>= 1) p += __shfl_xor_sync(0xffffffffu, p, o);
                if (lane == 0) {
                    float l = p + b2[j];
                    if (l > M) { S = S * expf(M - l) + 1.0f; M = l; }
                    else       { S += expf(l - M); }
                    float v = l + gum[j];
                    if (v > bv) { bv = v; bi = j; }
                }
            }
            if (lane == 0) { s_wM[wib] = M; s_wS[wib] = S; s_wBv[wib] = bv; s_wBi[wib] = bi; }
            __syncthreads();
            if (t == 0) {
                float M0 = s_wM[0], S0 = s_wS[0], bv0 = s_wBv[0];
                int bi0 = s_wBi[0];
#pragma unroll
                for (int w = 1; w < 8; w++) {
                    float M2 = s_wM[w], S2 = s_wS[w];
                    if (M2 > M0) { S0 = S0 * expf(M0 - M2) + S2; M0 = M2; }
                    else         { S0 += S2 * expf(M2 - M0); }
                    if (s_wBv[w] > bv0 || (s_wBv[w] == bv0 && s_wBi[w] < bi0)) {
                        bv0 = s_wBv[w]; bi0 = s_wBi[w];
                    }
                }
                d_pM[b] = M0; d_pS[b] = S0;
                unsigned long long key =
                    ((unsigned long long)ford(bv0) << 32) | (0xFFFFFFFFu - (unsigned)bi0);
                atomicMax(&d_amax, key);
            }
        }
        bar += NB; grid_sync(bar);

        // ---- phase C: merge + sample + next input (block 0 only) ----
        if (b == 0) {
            if (t < NB) { s_rM[t] = d_pM[t]; s_rS[t] = d_pS[t]; }
            __syncthreads();
            if (t == 0) {
                float Mg = -INFINITY;
                for (int i = 0; i < NB; i++) Mg = fmaxf(Mg, s_rM[i]);
                s_Mg = Mg;
                unsigned long long key = d_amax;
                s_act = (int)(0xFFFFFFFFu - (unsigned)(key & 0xFFFFFFFFull));
                d_amax = 0ull;
            }
            __syncthreads();
            int act = s_act;
            float Mg = s_Mg;
            // parallel sum of S_i * exp(M_i - Mg) and logit[act] recompute
            float part = (t < NB) ? s_rS[t] * expf(s_rM[t] - Mg) : 0.0f;
            float lp = (t < Dn) ? s_hrelu[t] * W2[(size_t)act * Dn + t] : 0.0f;
            s_rM[t] = part;       // reuse as scratch (256 slots? s_rM is 160) -> use s_red
            s_red[t] = part;
            s_red[256 + t] = lp;  // s_red has 1024 slots
            __syncthreads();
            for (int o = 128; o; o >>= 1) {
                if (t < o) {
                    s_red[t] += s_red[t + o];
                    s_red[256 + t] += s_red[256 + t + o];
                }
                __syncthreads();
            }
            if (t == 0) {
                float Sg = s_red[0];
                float logit = s_red[256] + b2[act];
                if (step < out_size) out[step] = (float)act;
                if (8 + step < out_size) out[8 + step] = logit - (Mg + logf(Sg));
            }
            if (t < Dn) s_inp[t] = emb[(size_t)act * Dn + t];
            __syncthreads();
        }
    }

    // ---- epilogue: write final h, c (block 0) ----
    if (b == 0 && t < Dn) {
        if (16 + t < out_size) out[16 + t] = s_h[t];
        if (144 + t < out_size) out[144 + t] = s_c[t];
    }
}

// ---------------- host launcher ----------------
extern "C" void kernel_launch(void* const* d_in, const int* in_sizes, int n_in,
                              void* d_out, int out_size) {
    const float* state = (const float*)d_in[0];
    const float* model = (const float*)d_in[1];
    const int*   ei    = (const int*)d_in[2];
    const float* W_l   = (const float*)d_in[3];
    const float* W_r   = (const float*)d_in[4];
    const float* att   = (const float*)d_in[5];
    const float* cbias = (const float*)d_in[6];
    const float* Wih   = (const float*)d_in[7];
    const float* Whh   = (const float*)d_in[8];
    const float* bih   = (const float*)d_in[9];
    const float* bhh   = (const float*)d_in[10];
    const float* pW1   = (const float*)d_in[11];
    const float* pb1   = (const float*)d_in[12];
    const float* pW2   = (const float*)d_in[13];
    const float* pb2   = (const float*)d_in[14];
    const float* emb   = (const float*)d_in[15];
    float* out = (float*)d_out;

    float* xl_ptr = nullptr;
    float* xr_ptr = nullptr;
    cudaGetSymbolAddress((void**)&xl_ptr, d_xl);
    cudaGetSymbolAddress((void**)&xr_ptr, d_xr);

    gumbel_kernel<<<(HORn * NMn + 255) / 256, 256>>>();
    init_kernel<<<(NSn + 255) / 256, 256>>>();

    gemm_xwt<<<(NSn + 63) / 64, 256>>>(state, W_l, xl_ptr, NSn);
    gemm_xwt<<<(NMn + 63) / 64, 256>>>(model, W_r, xr_ptr, NMn);

    edge_score_kernel<<<1024, 256>>>(ei, att);
    edge_exp_kernel<<<(En + 255) / 256, 256>>>(ei);
    edge_w_kernel<<<(En + 255) / 256, 256>>>(ei);

    policy_kernel<<<NB, 256>>>(state, W_l, cbias, Wih, Whh, bih, bhh,
                               pW1, pb1, pW2, pb2, emb, out, out_size);
}

// round 4
// speedup vs baseline: 1.4811x; 1.0413x over previous
#include <cuda_runtime.h>
#include <math.h>
#include <stdint.h>

#define NSn 100000
#define NMn 50000
#define En  600000
#define Dn  128
#define HORn 8
#define NB  148          // persistent-kernel blocks (<= SM count, all co-resident)
#define TINYF 1.17549435e-38f

#ifndef RNG_MODE
#define RNG_MODE 0
#endif

// ---------------- scratch (device globals; no allocation allowed) ----------------
__device__ float    d_xl[(size_t)NSn * Dn];   // 51.2 MB
__device__ float    d_xr[(size_t)NMn * Dn];   // 25.6 MB
__device__ float    d_e[En];                  // exp(score) per edge
__device__ float    d_s[NMn];                 // softmax denominators per dst
__device__ float    d_w[NSn];                 // per-source attention mass
__device__ float    d_v[Dn];                  // sum_s w_s * xl[s]
__device__ float    d_gum[(size_t)HORn * NMn];
__device__ float    d_hrelu[Dn];
__device__ float    d_pM[NB], d_pS[NB];       // per-block logsumexp partials
__device__ unsigned long long d_amax;         // packed argmax (ford(v)<<32 | ~idx)
__device__ unsigned d_bar_cnt;                // grid barrier counter (reset each replay)

// ---------------- f32x2 packed math helpers (Blackwell) ----------------
__device__ __forceinline__ unsigned long long ffma2(unsigned long long a,
                                                    unsigned long long b,
                                                    unsigned long long c) {
    unsigned long long d;
    asm("fma.rn.f32x2 %0, %1, %2, %3;" : "=l"(d) : "l"(a), "l"(b), "l"(c));
    return d;
}
__device__ __forceinline__ unsigned long long dup2(float x) {
    unsigned long long r;
    asm("mov.b64 %0, {%1, %1};" : "=l"(r) : "f"(x));
    return r;
}
__device__ __forceinline__ float2 unpack2(unsigned long long v) {
    float2 f;
    asm("mov.b64 {%0, %1}, %2;" : "=f"(f.x), "=f"(f.y) : "l"(v));
    return f;
}

// ---------------- threefry2x32 ----------------
__device__ __forceinline__ unsigned rotl32(unsigned x, int d) {
    return (x << d) | (x >> (32 - d));
}

__device__ __forceinline__ void tf2x32(unsigned k0, unsigned k1, unsigned c0, unsigned c1,
                                       unsigned& o0, unsigned& o1) {
    unsigned ks2 = k0 ^ k1 ^ 0x1BD11BDAu;
    unsigned x0 = c0 + k0, x1 = c1 + k1;
    const int ra[4] = {13, 15, 26, 6};
    const int rb[4] = {17, 29, 16, 24};
#pragma unroll
    for (int i = 0; i < 4; i++) { x0 += x1; x1 = rotl32(x1, ra[i]); x1 ^= x0; }
    x0 += k1; x1 += ks2 + 1u;
#pragma unroll
    for (int i = 0; i < 4; i++) { x0 += x1; x1 = rotl32(x1, rb[i]); x1 ^= x0; }
    x0 += ks2; x1 += k0 + 2u;
#pragma unroll
    for (int i = 0; i < 4; i++) { x0 += x1; x1 = rotl32(x1, ra[i]); x1 ^= x0; }
    x0 += k0; x1 += k1 + 3u;
#pragma unroll
    for (int i = 0; i < 4; i++) { x0 += x1; x1 = rotl32(x1, rb[i]); x1 ^= x0; }
    x0 += k1; x1 += ks2 + 4u;
#pragma unroll
    for (int i = 0; i < 4; i++) { x0 += x1; x1 = rotl32(x1, ra[i]); x1 ^= x0; }
    x0 += ks2; x1 += k0 + 5u;
    o0 = x0; o1 = x1;
}

// ---------------- setup: gumbel noise + zero all accumulators ----------------
__global__ void setup_kernel() {
    int idx = blockIdx.x * blockDim.x + threadIdx.x;

    // zero accumulators
    if (idx < NMn) d_s[idx] = 0.0f;
    if (idx < NSn) d_w[idx] = 0.0f;
    if (idx < Dn) d_v[idx] = 0.0f;
    if (idx == 0) { d_amax = 0ull; d_bar_cnt = 0u; }

    if (idx >= HORn * NMn) return;
    int step = idx / NMn;
    int i = idx - step * NMn;

    unsigned k0, k1;
#if RNG_MODE == 0
    tf2x32(0u, 42u, 0u, (unsigned)step, k0, k1);
#elif RNG_MODE == 1
    { unsigned a0, a1, b0, b1;
      tf2x32(0u, 42u, 0u, (unsigned)(2 * step), a0, a1);     k0 = a0 ^ a1;
      tf2x32(0u, 42u, 0u, (unsigned)(2 * step + 1), b0, b1); k1 = b0 ^ b1; }
#else
    { unsigned t0 = (unsigned)(2 * step), t1 = (unsigned)(2 * step + 1);
      unsigned p0, p1, q0, q1;
      if (t0 < 8) { tf2x32(0u, 42u, t0, t0 + 8u, p0, p1); k0 = p0; }
      else        { tf2x32(0u, 42u, t0 - 8u, t0, p0, p1); k0 = p1; }
      if (t1 < 8) { tf2x32(0u, 42u, t1, t1 + 8u, q0, q1); k1 = q0; }
      else        { tf2x32(0u, 42u, t1 - 8u, t1, q0, q1); k1 = q1; } }
#endif

    unsigned bits;
#if RNG_MODE == 2
    { unsigned c = (i < NMn / 2) ? (unsigned)i : (unsigned)(i - NMn / 2);
      unsigned o0, o1;
      tf2x32(k0, k1, c, c + (unsigned)(NMn / 2), o0, o1);
      bits = (i < NMn / 2) ? o0 : o1; }
#else
    { unsigned o0, o1;
      tf2x32(k0, k1, 0u, (unsigned)i, o0, o1);
      bits = o0 ^ o1; }
#endif

    float u = __uint_as_float((bits >> 9) | 0x3f800000u) - 1.0f;
    u = u + TINYF;
    u = fmaxf(TINYF, u);
    d_gum[idx] = -logf(-logf(u));
}

// ---------------- float ordered-int helper ----------------
__device__ __forceinline__ unsigned ford(float f) {
    unsigned u = __float_as_uint(f);
    return (u & 0x80000000u) ? ~u : (u | 0x80000000u);
}

// ---------------- GEMM: C[N,128] = A[N,128] * W[128,128]^T  (f32x2 packed) ----------------
__global__ __launch_bounds__(256) void gemm_xwt(const float* __restrict__ A,
                                                const float* __restrict__ W,
                                                float* __restrict__ C, int N) {
    __shared__ __align__(16) float As[16][128];
    __shared__ __align__(16) float Ws[16][128];
    int tid = threadIdx.x;
    int tn = tid & 31, tm = tid >> 5;
    int rowBase = blockIdx.x * 128;

    unsigned long long acc[8][4];
#pragma unroll
    for (int i = 0; i < 8; i++)
#pragma unroll
        for (int j = 0; j < 4; j++) acc[i][j] = 0ull;

    for (int k0 = 0; k0 < Dn; k0 += 16) {
        // load A tile: 128 rows x 16 k  (2 float4 per thread)
#pragma unroll
        for (int r = 0; r < 2; r++) {
            int q = tid + 256 * r;          // 0..511
            int row = q >> 2; int kq = (q & 3) * 4;
            int ar = rowBase + row; if (ar >= N) ar = N - 1;
            float4 av = *(const float4*)(A + (size_t)ar * Dn + k0 + kq);
            As[kq + 0][row] = av.x; As[kq + 1][row] = av.y;
            As[kq + 2][row] = av.z; As[kq + 3][row] = av.w;
        }
        // load W tile: 128 cols x 16 k
#pragma unroll
        for (int r = 0; r < 2; r++) {
            int q = tid + 256 * r;
            int col = q >> 2; int kq = (q & 3) * 4;
            float4 wv = *(const float4*)(W + (size_t)col * Dn + k0 + kq);
            Ws[kq + 0][col] = wv.x; Ws[kq + 1][col] = wv.y;
            Ws[kq + 2][col] = wv.z; Ws[kq + 3][col] = wv.w;
        }
        __syncthreads();
#pragma unroll
        for (int kk = 0; kk < 16; kk++) {
            float4 bq = *(const float4*)&Ws[kk][tn * 4];
            unsigned long long bd0 = dup2(bq.x), bd1 = dup2(bq.y);
            unsigned long long bd2 = dup2(bq.z), bd3 = dup2(bq.w);
#pragma unroll
            for (int ip = 0; ip < 8; ip++) {
                unsigned long long a2 =
                    *(const unsigned long long*)&As[kk][tm * 16 + ip * 2];
                acc[ip][0] = ffma2(a2, bd0, acc[ip][0]);
                acc[ip][1] = ffma2(a2, bd1, acc[ip][1]);
                acc[ip][2] = ffma2(a2, bd2, acc[ip][2]);
                acc[ip][3] = ffma2(a2, bd3, acc[ip][3]);
            }
        }
        __syncthreads();
    }
#pragma unroll
    for (int ip = 0; ip < 8; ip++) {
        float2 c0 = unpack2(acc[ip][0]);
        float2 c1 = unpack2(acc[ip][1]);
        float2 c2 = unpack2(acc[ip][2]);
        float2 c3 = unpack2(acc[ip][3]);
        int r0 = rowBase + tm * 16 + ip * 2;
        if (r0 < N)
            *(float4*)(C + (size_t)r0 * Dn + tn * 4) = make_float4(c0.x, c1.x, c2.x, c3.x);
        if (r0 + 1 < N)
            *(float4*)(C + (size_t)(r0 + 1) * Dn + tn * 4) = make_float4(c0.y, c1.y, c2.y, c3.y);
    }
}

// ---------------- edge pass 1: ex = exp(att . leakyrelu(xl[src]+xr[dst])); s[d] += ex ----------------
// half-warp per edge (16 lanes x 2 float4 = 128 floats)
__global__ void edge_score_exp(const int* __restrict__ ei,
                               const float* __restrict__ att) {
    int lane = threadIdx.x & 31;
    int sl = lane & 15, sub = lane >> 4;
    int warp = (blockIdx.x * blockDim.x + threadIdx.x) >> 5;
    int nwarps = (gridDim.x * blockDim.x) >> 5;
    float4 a0 = ((const float4*)att)[sl];
    float4 a1 = ((const float4*)att)[sl + 16];
    for (int eb = warp; eb < En / 2; eb += nwarps) {
        int e = eb * 2 + sub;
        int s = ei[e];
        int d = ei[En + e];
        const float4* rl = (const float4*)(d_xl + (size_t)s * Dn);
        const float4* rr = (const float4*)(d_xr + (size_t)d * Dn);
        float4 x0 = rl[sl], x1 = rl[sl + 16];
        float4 y0 = rr[sl], y1 = rr[sl + 16];
        float z;
        float p = 0.0f;
        z = x0.x + y0.x; p += ((z > 0.f) ? z : 0.2f * z) * a0.x;
        z = x0.y + y0.y; p += ((z > 0.f) ? z : 0.2f * z) * a0.y;
        z = x0.z + y0.z; p += ((z > 0.f) ? z : 0.2f * z) * a0.z;
        z = x0.w + y0.w; p += ((z > 0.f) ? z : 0.2f * z) * a0.w;
        z = x1.x + y1.x; p += ((z > 0.f) ? z : 0.2f * z) * a1.x;
        z = x1.y + y1.y; p += ((z > 0.f) ? z : 0.2f * z) * a1.y;
        z = x1.z + y1.z; p += ((z > 0.f) ? z : 0.2f * z) * a1.z;
        z = x1.w + y1.w; p += ((z > 0.f) ? z : 0.2f * z) * a1.w;
#pragma unroll
        for (int o = 8; o; o >>= 1) p += __shfl_xor_sync(0xffffffffu, p, o);
        if (sl == 0) {
            float ex = expf(p);
            d_e[e] = ex;
            atomicAdd(&d_s[d], ex);
        }
    }
}

// ---------------- edge pass 2: w[src] += ex / s[dst] ----------------
__global__ void edge_w_kernel(const int* __restrict__ ei) {
    int e = blockIdx.x * blockDim.x + threadIdx.x;
    if (e >= En) return;
    int s = ei[e];
    int d = ei[En + e];
    atomicAdd(&d_w[s], d_e[e] / d_s[d]);
}

// ---------------- persistent fused policy kernel ----------------
__device__ __forceinline__ float sigm(float x) { return 1.0f / (1.0f + expf(-x)); }

__device__ __forceinline__ void grid_sync(unsigned target) {
    __syncthreads();
    if (threadIdx.x == 0) {
        __threadfence();
        atomicAdd(&d_bar_cnt, 1u);
        while (*((volatile unsigned*)&d_bar_cnt) < target) { }
        __threadfence();
    }
    __syncthreads();
}

__global__ __launch_bounds__(256) void policy_kernel(
    const float* __restrict__ cbias,
    const float* __restrict__ Wih, const float* __restrict__ Whh,
    const float* __restrict__ bih, const float* __restrict__ bhh,
    const float* __restrict__ W1,  const float* __restrict__ b1,
    const float* __restrict__ W2,  const float* __restrict__ b2,
    const float* __restrict__ emb,
    float* __restrict__ out, int out_size)
{
    __shared__ float s_inp[Dn], s_h[Dn], s_c[Dn], s_hrelu[Dn];
    __shared__ float s_gates[4 * Dn];
    __shared__ float s_red[8 * Dn];
    __shared__ float s_wM[8], s_wS[8], s_wBv[8];
    __shared__ int   s_wBi[8];
    __shared__ float s_rM[160], s_rS[160];
    __shared__ int   s_act;
    __shared__ float s_Mg;

    const int t = threadIdx.x;
    const int lane = t & 31;
    const int wib = t >> 5;
    const int b = blockIdx.x;
    unsigned bar = 0;

    // ---- prologue: v = sum_s w_s * xl[s] (all blocks); == W_l @ (sum w_s state_s) ----
    {
        int gw = b * 8 + wib;
        float4 acc = make_float4(0.f, 0.f, 0.f, 0.f);
        for (int s = gw; s < NSn; s += NB * 8) {
            float ws = d_w[s];
            if (ws != 0.0f) {
                float4 x = ((const float4*)(d_xl + (size_t)s * Dn))[lane];
                acc.x += ws * x.x; acc.y += ws * x.y;
                acc.z += ws * x.z; acc.w += ws * x.w;
            }
        }
        s_red[wib * Dn + lane * 4 + 0] = acc.x;
        s_red[wib * Dn + lane * 4 + 1] = acc.y;
        s_red[wib * Dn + lane * 4 + 2] = acc.z;
        s_red[wib * Dn + lane * 4 + 3] = acc.w;
        __syncthreads();
        if (t < Dn) {
            float v = 0.0f;
#pragma unroll
            for (int w = 0; w < 8; w++) v += s_red[w * Dn + t];
            atomicAdd(&d_v[t], v);
        }
    }
    bar += NB; grid_sync(bar);

    // ---- block 0: g = v/NM + cbias ; h=c=0 ----
    if (b == 0) {
        if (t < Dn) {
            s_inp[t] = d_v[t] * (1.0f / (float)NMn) + cbias[t];
            s_h[t] = 0.0f; s_c[t] = 0.0f;
        }
        __syncthreads();
    }

    const int chunk = (NMn + NB - 1) / NB;       // 338
    const int row0 = b * chunk;
    const int row1 = (row0 + chunk < NMn) ? (row0 + chunk) : NMn;

    for (int step = 0; step < HORn; step++) {
        // ---- phase A: LSTM + MLP1 (block 0 only) ----
        if (b == 0) {
#pragma unroll
            for (int rr = 0; rr < 2; rr++) {
                int r = t + rr * 256;
                float a = bih[r] + bhh[r];
                const float4* wi = (const float4*)(Wih + (size_t)r * Dn);
                const float4* wh = (const float4*)(Whh + (size_t)r * Dn);
                const float4* pi = (const float4*)s_inp;
                const float4* ph = (const float4*)s_h;
#pragma unroll 8
                for (int k = 0; k < Dn / 4; k++) {
                    float4 w4 = wi[k]; float4 i4 = pi[k];
                    a += w4.x * i4.x + w4.y * i4.y + w4.z * i4.z + w4.w * i4.w;
                    float4 v4 = wh[k]; float4 h4 = ph[k];
                    a += v4.x * h4.x + v4.y * h4.y + v4.z * h4.z + v4.w * h4.w;
                }
                s_gates[r] = a;
            }
            __syncthreads();
            if (t < Dn) {
                float ig = sigm(s_gates[t]);
                float fg = sigm(s_gates[Dn + t]);
                float gg = tanhf(s_gates[2 * Dn + t]);
                float og = sigm(s_gates[3 * Dn + t]);
                float c = fg * s_c[t] + ig * gg;
                float h = og * tanhf(c);
                s_c[t] = c; s_h[t] = h;
            }
            __syncthreads();
            if (t < Dn) {
                float a = b1[t];
                const float4* wr = (const float4*)(W1 + (size_t)t * Dn);
                const float4* ph = (const float4*)s_h;
#pragma unroll 8
                for (int k = 0; k < Dn / 4; k++) {
                    float4 w4 = wr[k]; float4 h4 = ph[k];
                    a += w4.x * h4.x + w4.y * h4.y + w4.z * h4.z + w4.w * h4.w;
                }
                d_hrelu[t] = fmaxf(a, 0.0f);
            }
        }
        bar += NB; grid_sync(bar);

        // ---- phase B: logits chunk + partial logsumexp + argmax (all blocks) ----
        if (t < Dn) s_hrelu[t] = d_hrelu[t];
        __syncthreads();
        {
            float4 h4 = ((const float4*)s_hrelu)[lane];
            const float* gum = d_gum + (size_t)step * NMn;
            float M = -INFINITY, S = 0.0f, bv = -INFINITY;
            int bi = 0;
            for (int j = row0 + wib; j < row1; j += 8) {
                float4 w4 = ((const float4*)(W2 + (size_t)j * Dn))[lane];
                float p = w4.x * h4.x + w4.y * h4.y + w4.z * h4.z + w4.w * h4.w;
#pragma unroll
                for (int o = 16; o; o >>= 1) p += __shfl_xor_sync(0xffffffffu, p, o);
                if (lane == 0) {
                    float l = p + b2[j];
                    if (l > M) { S = S * expf(M - l) + 1.0f; M = l; }
                    else       { S += expf(l - M); }
                    float v = l + gum[j];
                    if (v > bv) { bv = v; bi = j; }
                }
            }
            if (lane == 0) { s_wM[wib] = M; s_wS[wib] = S; s_wBv[wib] = bv; s_wBi[wib] = bi; }
            __syncthreads();
            if (t == 0) {
                float M0 = s_wM[0], S0 = s_wS[0], bv0 = s_wBv[0];
                int bi0 = s_wBi[0];
#pragma unroll
                for (int w = 1; w < 8; w++) {
                    float M2 = s_wM[w], S2 = s_wS[w];
                    if (M2 > M0) { S0 = S0 * expf(M0 - M2) + S2; M0 = M2; }
                    else         { S0 += S2 * expf(M2 - M0); }
                    if (s_wBv[w] > bv0 || (s_wBv[w] == bv0 && s_wBi[w] < bi0)) {
                        bv0 = s_wBv[w]; bi0 = s_wBi[w];
                    }
                }
                d_pM[b] = M0; d_pS[b] = S0;
                unsigned long long key =
                    ((unsigned long long)ford(bv0) << 32) | (0xFFFFFFFFu - (unsigned)bi0);
                atomicMax(&d_amax, key);
            }
        }
        bar += NB; grid_sync(bar);

        // ---- phase C: merge + sample + next input (block 0 only) ----
        if (b == 0) {
            if (t < NB) { s_rM[t] = d_pM[t]; s_rS[t] = d_pS[t]; }
            __syncthreads();
            if (t == 0) {
                float Mg = -INFINITY;
                for (int i = 0; i < NB; i++) Mg = fmaxf(Mg, s_rM[i]);
                s_Mg = Mg;
                unsigned long long key = d_amax;
                s_act = (int)(0xFFFFFFFFu - (unsigned)(key & 0xFFFFFFFFull));
                d_amax = 0ull;
            }
            __syncthreads();
            int act = s_act;
            float Mg = s_Mg;
            float part = (t < NB) ? s_rS[t] * expf(s_rM[t] - Mg) : 0.0f;
            float lp = (t < Dn) ? s_hrelu[t] * W2[(size_t)act * Dn + t] : 0.0f;
            s_red[t] = part;
            s_red[256 + t] = lp;
            __syncthreads();
            for (int o = 128; o; o >>= 1) {
                if (t < o) {
                    s_red[t] += s_red[t + o];
                    s_red[256 + t] += s_red[256 + t + o];
                }
                __syncthreads();
            }
            if (t == 0) {
                float Sg = s_red[0];
                float logit = s_red[256] + b2[act];
                if (step < out_size) out[step] = (float)act;
                if (8 + step < out_size) out[8 + step] = logit - (Mg + logf(Sg));
            }
            if (t < Dn) s_inp[t] = emb[(size_t)act * Dn + t];
            __syncthreads();
        }
    }

    // ---- epilogue: write final h, c (block 0) ----
    if (b == 0 && t < Dn) {
        if (16 + t < out_size) out[16 + t] = s_h[t];
        if (144 + t < out_size) out[144 + t] = s_c[t];
    }
}

// ---------------- host launcher ----------------
extern "C" void kernel_launch(void* const* d_in, const int* in_sizes, int n_in,
                              void* d_out, int out_size) {
    const float* state = (const float*)d_in[0];
    const float* model = (const float*)d_in[1];
    const int*   ei    = (const int*)d_in[2];
    const float* W_l   = (const float*)d_in[3];
    const float* W_r   = (const float*)d_in[4];
    const float* att   = (const float*)d_in[5];
    const float* cbias = (const float*)d_in[6];
    const float* Wih   = (const float*)d_in[7];
    const float* Whh   = (const float*)d_in[8];
    const float* bih   = (const float*)d_in[9];
    const float* bhh   = (const float*)d_in[10];
    const float* pW1   = (const float*)d_in[11];
    const float* pb1   = (const float*)d_in[12];
    const float* pW2   = (const float*)d_in[13];
    const float* pb2   = (const float*)d_in[14];
    const float* emb   = (const float*)d_in[15];
    float* out = (float*)d_out;

    float* xl_ptr = nullptr;
    float* xr_ptr = nullptr;
    cudaGetSymbolAddress((void**)&xl_ptr, d_xl);
    cudaGetSymbolAddress((void**)&xr_ptr, d_xr);

    setup_kernel<<<(HORn * NMn + 255) / 256, 256>>>();

    gemm_xwt<<<(NSn + 127) / 128, 256>>>(state, W_l, xl_ptr, NSn);
    gemm_xwt<<<(NMn + 127) / 128, 256>>>(model, W_r, xr_ptr, NMn);

    edge_score_exp<<<1024, 256>>>(ei, att);
    edge_w_kernel<<<(En + 255) / 256, 256>>>(ei);

    policy_kernel<<<NB, 256>>>(cbias, Wih, Whh, bih, bhh,
                               pW1, pb1, pW2, pb2, emb, out, out_size);
}

// round 5
// speedup vs baseline: 2.0985x; 1.4168x over previous
#include <cuda_runtime.h>
#include <math.h>
#include <stdint.h>

#define NSn 100000
#define NMn 50000
#define En  600000
#define Dn  128
#define HORn 8
#define NB  148          // persistent-kernel blocks (<= SM count, all co-resident)
#define PTH 1024         // policy kernel threads per block
#define TINYF 1.17549435e-38f

#ifndef RNG_MODE
#define RNG_MODE 0
#endif

// ---------------- scratch (device globals; no allocation allowed) ----------------
__device__ float    d_xl[(size_t)NSn * Dn];   // 51.2 MB
__device__ float    d_xr[(size_t)NMn * Dn];   // 25.6 MB
__device__ float    d_e[En];                  // exp(score) per edge
__device__ float    d_s[NMn];                 // softmax denominators per dst
__device__ float    d_w[NSn];                 // per-source attention mass
__device__ float    d_v[Dn];                  // sum_s w_s * xl[s]
__device__ float    d_gum[(size_t)HORn * NMn];
__device__ float    d_hrelu[Dn];
__device__ float    d_pM[NB], d_pS[NB];       // per-block logsumexp partials
__device__ unsigned long long d_amax;         // packed argmax (ford(v)<<32 | ~idx)
__device__ unsigned d_bar_cnt;                // grid barrier counter (reset each replay)

// ---------------- f32x2 packed math helpers (Blackwell) ----------------
__device__ __forceinline__ unsigned long long ffma2(unsigned long long a,
                                                    unsigned long long b,
                                                    unsigned long long c) {
    unsigned long long d;
    asm("fma.rn.f32x2 %0, %1, %2, %3;" : "=l"(d) : "l"(a), "l"(b), "l"(c));
    return d;
}
__device__ __forceinline__ unsigned long long dup2(float x) {
    unsigned long long r;
    asm("mov.b64 %0, {%1, %1};" : "=l"(r) : "f"(x));
    return r;
}
__device__ __forceinline__ float2 unpack2(unsigned long long v) {
    float2 f;
    asm("mov.b64 {%0, %1}, %2;" : "=f"(f.x), "=f"(f.y) : "l"(v));
    return f;
}

// ---------------- threefry2x32 ----------------
__device__ __forceinline__ unsigned rotl32(unsigned x, int d) {
    return (x << d) | (x >> (32 - d));
}

__device__ __forceinline__ void tf2x32(unsigned k0, unsigned k1, unsigned c0, unsigned c1,
                                       unsigned& o0, unsigned& o1) {
    unsigned ks2 = k0 ^ k1 ^ 0x1BD11BDAu;
    unsigned x0 = c0 + k0, x1 = c1 + k1;
    const int ra[4] = {13, 15, 26, 6};
    const int rb[4] = {17, 29, 16, 24};
#pragma unroll
    for (int i = 0; i < 4; i++) { x0 += x1; x1 = rotl32(x1, ra[i]); x1 ^= x0; }
    x0 += k1; x1 += ks2 + 1u;
#pragma unroll
    for (int i = 0; i < 4; i++) { x0 += x1; x1 = rotl32(x1, rb[i]); x1 ^= x0; }
    x0 += ks2; x1 += k0 + 2u;
#pragma unroll
    for (int i = 0; i < 4; i++) { x0 += x1; x1 = rotl32(x1, ra[i]); x1 ^= x0; }
    x0 += k0; x1 += k1 + 3u;
#pragma unroll
    for (int i = 0; i < 4; i++) { x0 += x1; x1 = rotl32(x1, rb[i]); x1 ^= x0; }
    x0 += k1; x1 += ks2 + 4u;
#pragma unroll
    for (int i = 0; i < 4; i++) { x0 += x1; x1 = rotl32(x1, ra[i]); x1 ^= x0; }
    x0 += ks2; x1 += k0 + 5u;
    o0 = x0; o1 = x1;
}

// ---------------- setup: gumbel noise + zero all accumulators ----------------
__global__ void setup_kernel() {
    int idx = blockIdx.x * blockDim.x + threadIdx.x;

    if (idx < NMn) d_s[idx] = 0.0f;
    if (idx < NSn) d_w[idx] = 0.0f;
    if (idx < Dn) d_v[idx] = 0.0f;
    if (idx == 0) { d_amax = 0ull; d_bar_cnt = 0u; }

    if (idx >= HORn * NMn) return;
    int step = idx / NMn;
    int i = idx - step * NMn;

    unsigned k0, k1;
#if RNG_MODE == 0
    tf2x32(0u, 42u, 0u, (unsigned)step, k0, k1);
#elif RNG_MODE == 1
    { unsigned a0, a1, b0, b1;
      tf2x32(0u, 42u, 0u, (unsigned)(2 * step), a0, a1);     k0 = a0 ^ a1;
      tf2x32(0u, 42u, 0u, (unsigned)(2 * step + 1), b0, b1); k1 = b0 ^ b1; }
#else
    { unsigned t0 = (unsigned)(2 * step), t1 = (unsigned)(2 * step + 1);
      unsigned p0, p1, q0, q1;
      if (t0 < 8) { tf2x32(0u, 42u, t0, t0 + 8u, p0, p1); k0 = p0; }
      else        { tf2x32(0u, 42u, t0 - 8u, t0, p0, p1); k0 = p1; }
      if (t1 < 8) { tf2x32(0u, 42u, t1, t1 + 8u, q0, q1); k1 = q0; }
      else        { tf2x32(0u, 42u, t1 - 8u, t1, q0, q1); k1 = q1; } }
#endif

    unsigned bits;
#if RNG_MODE == 2
    { unsigned c = (i < NMn / 2) ? (unsigned)i : (unsigned)(i - NMn / 2);
      unsigned o0, o1;
      tf2x32(k0, k1, c, c + (unsigned)(NMn / 2), o0, o1);
      bits = (i < NMn / 2) ? o0 : o1; }
#else
    { unsigned o0, o1;
      tf2x32(k0, k1, 0u, (unsigned)i, o0, o1);
      bits = o0 ^ o1; }
#endif

    float u = __uint_as_float((bits >> 9) | 0x3f800000u) - 1.0f;
    u = u + TINYF;
    u = fmaxf(TINYF, u);
    d_gum[idx] = -logf(-logf(u));
}

// ---------------- float ordered-int helper ----------------
__device__ __forceinline__ unsigned ford(float f) {
    unsigned u = __float_as_uint(f);
    return (u & 0x80000000u) ? ~u : (u | 0x80000000u);
}

// ---------------- GEMM: C[N,128] = A[N,128] * W[128,128]^T  (f32x2 packed) ----------------
__global__ __launch_bounds__(256) void gemm_xwt(const float* __restrict__ A,
                                                const float* __restrict__ W,
                                                float* __restrict__ C, int N) {
    __shared__ __align__(16) float As[16][128];
    __shared__ __align__(16) float Ws[16][128];
    int tid = threadIdx.x;
    int tn = tid & 31, tm = tid >> 5;
    int rowBase = blockIdx.x * 128;

    unsigned long long acc[8][4];
#pragma unroll
    for (int i = 0; i < 8; i++)
#pragma unroll
        for (int j = 0; j < 4; j++) acc[i][j] = 0ull;

    for (int k0 = 0; k0 < Dn; k0 += 16) {
#pragma unroll
        for (int r = 0; r < 2; r++) {
            int q = tid + 256 * r;
            int row = q >> 2; int kq = (q & 3) * 4;
            int ar = rowBase + row; if (ar >= N) ar = N - 1;
            float4 av = *(const float4*)(A + (size_t)ar * Dn + k0 + kq);
            As[kq + 0][row] = av.x; As[kq + 1][row] = av.y;
            As[kq + 2][row] = av.z; As[kq + 3][row] = av.w;
        }
#pragma unroll
        for (int r = 0; r < 2; r++) {
            int q = tid + 256 * r;
            int col = q >> 2; int kq = (q & 3) * 4;
            float4 wv = *(const float4*)(W + (size_t)col * Dn + k0 + kq);
            Ws[kq + 0][col] = wv.x; Ws[kq + 1][col] = wv.y;
            Ws[kq + 2][col] = wv.z; Ws[kq + 3][col] = wv.w;
        }
        __syncthreads();
#pragma unroll
        for (int kk = 0; kk < 16; kk++) {
            float4 bq = *(const float4*)&Ws[kk][tn * 4];
            unsigned long long bd0 = dup2(bq.x), bd1 = dup2(bq.y);
            unsigned long long bd2 = dup2(bq.z), bd3 = dup2(bq.w);
#pragma unroll
            for (int ip = 0; ip < 8; ip++) {
                unsigned long long a2 =
                    *(const unsigned long long*)&As[kk][tm * 16 + ip * 2];
                acc[ip][0] = ffma2(a2, bd0, acc[ip][0]);
                acc[ip][1] = ffma2(a2, bd1, acc[ip][1]);
                acc[ip][2] = ffma2(a2, bd2, acc[ip][2]);
                acc[ip][3] = ffma2(a2, bd3, acc[ip][3]);
            }
        }
        __syncthreads();
    }
#pragma unroll
    for (int ip = 0; ip < 8; ip++) {
        float2 c0 = unpack2(acc[ip][0]);
        float2 c1 = unpack2(acc[ip][1]);
        float2 c2 = unpack2(acc[ip][2]);
        float2 c3 = unpack2(acc[ip][3]);
        int r0 = rowBase + tm * 16 + ip * 2;
        if (r0 < N)
            *(float4*)(C + (size_t)r0 * Dn + tn * 4) = make_float4(c0.x, c1.x, c2.x, c3.x);
        if (r0 + 1 < N)
            *(float4*)(C + (size_t)(r0 + 1) * Dn + tn * 4) = make_float4(c0.y, c1.y, c2.y, c3.y);
    }
}

// ---------------- edge pass 1: warp per 4 edges (ILP), s[d] += exp(score) ----------------
__device__ __forceinline__ float lrelu_dot(float4 x, float4 y, float4 a) {
    float z, p = 0.0f;
    z = x.x + y.x; p += ((z > 0.f) ? z : 0.2f * z) * a.x;
    z = x.y + y.y; p += ((z > 0.f) ? z : 0.2f * z) * a.y;
    z = x.z + y.z; p += ((z > 0.f) ? z : 0.2f * z) * a.z;
    z = x.w + y.w; p += ((z > 0.f) ? z : 0.2f * z) * a.w;
    return p;
}

__global__ void edge_score_exp(const int* __restrict__ ei,
                               const float* __restrict__ att) {
    int lane = threadIdx.x & 31;
    int warp = (blockIdx.x * blockDim.x + threadIdx.x) >> 5;
    int nwarps = (gridDim.x * blockDim.x) >> 5;
    float4 a4 = ((const float4*)att)[lane];
    for (int base = warp * 4; base < En; base += nwarps * 4) {
        int s0 = ei[base + 0], s1 = ei[base + 1], s2 = ei[base + 2], s3 = ei[base + 3];
        int d0 = ei[En + base + 0], d1 = ei[En + base + 1];
        int d2 = ei[En + base + 2], d3 = ei[En + base + 3];
        float4 xl0 = ((const float4*)(d_xl + (size_t)s0 * Dn))[lane];
        float4 xl1 = ((const float4*)(d_xl + (size_t)s1 * Dn))[lane];
        float4 xl2 = ((const float4*)(d_xl + (size_t)s2 * Dn))[lane];
        float4 xl3 = ((const float4*)(d_xl + (size_t)s3 * Dn))[lane];
        float4 xr0 = ((const float4*)(d_xr + (size_t)d0 * Dn))[lane];
        float4 xr1 = ((const float4*)(d_xr + (size_t)d1 * Dn))[lane];
        float4 xr2 = ((const float4*)(d_xr + (size_t)d2 * Dn))[lane];
        float4 xr3 = ((const float4*)(d_xr + (size_t)d3 * Dn))[lane];
        float p0 = lrelu_dot(xl0, xr0, a4);
        float p1 = lrelu_dot(xl1, xr1, a4);
        float p2 = lrelu_dot(xl2, xr2, a4);
        float p3 = lrelu_dot(xl3, xr3, a4);
#pragma unroll
        for (int o = 16; o; o >>= 1) {
            p0 += __shfl_xor_sync(0xffffffffu, p0, o);
            p1 += __shfl_xor_sync(0xffffffffu, p1, o);
            p2 += __shfl_xor_sync(0xffffffffu, p2, o);
            p3 += __shfl_xor_sync(0xffffffffu, p3, o);
        }
        if (lane == 0) {
            float e0 = expf(p0), e1 = expf(p1), e2 = expf(p2), e3 = expf(p3);
            d_e[base + 0] = e0; d_e[base + 1] = e1;
            d_e[base + 2] = e2; d_e[base + 3] = e3;
            atomicAdd(&d_s[d0], e0);
            atomicAdd(&d_s[d1], e1);
            atomicAdd(&d_s[d2], e2);
            atomicAdd(&d_s[d3], e3);
        }
    }
}

// ---------------- edge pass 2: w[src] += ex / s[dst] ----------------
__global__ void edge_w_kernel(const int* __restrict__ ei) {
    int e = blockIdx.x * blockDim.x + threadIdx.x;
    if (e >= En) return;
    int s = ei[e];
    int d = ei[En + e];
    atomicAdd(&d_w[s], d_e[e] / d_s[d]);
}

// ---------------- persistent fused policy kernel ----------------
__device__ __forceinline__ float sigm(float x) { return 1.0f / (1.0f + expf(-x)); }

__device__ __forceinline__ void lse_merge(float& M, float& S, float M2, float S2) {
    if (M2 == -INFINITY) return;
    if (M == -INFINITY) { M = M2; S = S2; return; }
    if (M2 > M) { S = S * expf(M - M2) + S2; M = M2; }
    else        { S += S2 * expf(M2 - M); }
}

__device__ __forceinline__ void grid_sync(unsigned target) {
    __syncthreads();
    if (threadIdx.x == 0) {
        __threadfence();
        atomicAdd(&d_bar_cnt, 1u);
        while (*((volatile unsigned*)&d_bar_cnt) < target) { }
        __threadfence();
    }
    __syncthreads();
}

__global__ __launch_bounds__(PTH, 1) void policy_kernel(
    const float* __restrict__ cbias,
    const float* __restrict__ Wih, const float* __restrict__ Whh,
    const float* __restrict__ bih, const float* __restrict__ bhh,
    const float* __restrict__ W1,  const float* __restrict__ b1,
    const float* __restrict__ W2,  const float* __restrict__ b2,
    const float* __restrict__ emb,
    float* __restrict__ out, int out_size)
{
    __shared__ float s_inp[Dn], s_h[Dn], s_c[Dn], s_hrelu[Dn];
    __shared__ float s_gates[4 * Dn];
    __shared__ __align__(16) float s_red[32 * Dn];   // 16 KB scratch
    __shared__ float s_wM[32], s_wS[32];
    __shared__ unsigned long long s_wK[32];
    __shared__ float s_cM, s_cS;
    __shared__ int   s_act;

    const int t = threadIdx.x;
    const int lane = t & 31;
    const int wib = t >> 5;           // 0..31
    const int b = blockIdx.x;
    unsigned bar = 0;

    // ---- prologue: v = sum_s w_s * xl[s] (all blocks, 32 warps each) ----
    {
        int gw = b * 32 + wib;
        float4 acc = make_float4(0.f, 0.f, 0.f, 0.f);
        for (int s = gw; s < NSn; s += NB * 32) {
            float ws = d_w[s];
            if (ws != 0.0f) {
                float4 x = ((const float4*)(d_xl + (size_t)s * Dn))[lane];
                acc.x += ws * x.x; acc.y += ws * x.y;
                acc.z += ws * x.z; acc.w += ws * x.w;
            }
        }
        s_red[wib * Dn + lane * 4 + 0] = acc.x;
        s_red[wib * Dn + lane * 4 + 1] = acc.y;
        s_red[wib * Dn + lane * 4 + 2] = acc.z;
        s_red[wib * Dn + lane * 4 + 3] = acc.w;
        __syncthreads();
        if (t < Dn) {
            float v = 0.0f;
#pragma unroll
            for (int w = 0; w < 32; w++) v += s_red[w * Dn + t];
            atomicAdd(&d_v[t], v);
        }
    }
    bar += NB; grid_sync(bar);

    // ---- block 0: initial LSTM input g = v/NM + cbias; h=c=0 ----
    if (b == 0) {
        if (t < Dn) {
            s_inp[t] = d_v[t] * (1.0f / (float)NMn) + cbias[t];
            s_h[t] = 0.0f; s_c[t] = 0.0f;
        }
        __syncthreads();
    }

    const int chunk = (NMn + NB - 1) / NB;        // 338
    const int row0 = b * chunk;
    const int row1 = (row0 + chunk < NMn) ? (row0 + chunk) : NMn;
    const int g8 = lane >> 3;                     // row group 0..3
    const int l8 = lane & 7;                      // lane within group
    const bool leader = (l8 == 0);

    for (int step = 0; step < HORn; step++) {
        // ---- phase A: LSTM + MLP1 (block 0) ----
        if (b == 0) {
            if (t < 4 * Dn) {
                int r = t;
                float a = bih[r] + bhh[r];
                const float4* wi = (const float4*)(Wih + (size_t)r * Dn);
                const float4* wh = (const float4*)(Whh + (size_t)r * Dn);
                const float4* pi = (const float4*)s_inp;
                const float4* ph = (const float4*)s_h;
#pragma unroll 8
                for (int k = 0; k < Dn / 4; k++) {
                    float4 w4 = wi[k]; float4 i4 = pi[k];
                    a += w4.x * i4.x + w4.y * i4.y + w4.z * i4.z + w4.w * i4.w;
                    float4 v4 = wh[k]; float4 h4 = ph[k];
                    a += v4.x * h4.x + v4.y * h4.y + v4.z * h4.z + v4.w * h4.w;
                }
                s_gates[r] = a;
            }
            __syncthreads();
            if (t < Dn) {
                float ig = sigm(s_gates[t]);
                float fg = sigm(s_gates[Dn + t]);
                float gg = tanhf(s_gates[2 * Dn + t]);
                float og = sigm(s_gates[3 * Dn + t]);
                float c = fg * s_c[t] + ig * gg;
                float h = og * tanhf(c);
                s_c[t] = c; s_h[t] = h;
            }
            __syncthreads();
            if (t < Dn) {
                float a = b1[t];
                const float4* wr = (const float4*)(W1 + (size_t)t * Dn);
                const float4* ph = (const float4*)s_h;
#pragma unroll 8
                for (int k = 0; k < Dn / 4; k++) {
                    float4 w4 = wr[k]; float4 h4 = ph[k];
                    a += w4.x * h4.x + w4.y * h4.y + w4.z * h4.z + w4.w * h4.w;
                }
                d_hrelu[t] = fmaxf(a, 0.0f);
            }
        }
        bar += NB; grid_sync(bar);

        // ---- phase B: logits + online lse + argmax (all blocks, 4 rows/warp-iter) ----
        if (t < Dn) s_hrelu[t] = d_hrelu[t];
        __syncthreads();
        {
            const float4* hp = (const float4*)s_hrelu;
            float4 h0 = hp[l8 * 4 + 0], h1 = hp[l8 * 4 + 1];
            float4 h2 = hp[l8 * 4 + 2], h3 = hp[l8 * 4 + 3];
            const float* gum = d_gum + (size_t)step * NMn;
            float M = -INFINITY, S = 0.0f;
            unsigned long long key = 0ull;

            for (int j = row0 + wib * 4; j < row1; j += 32 * 4) {
                int r = j + g8;
                float p = 0.0f;
                if (r < row1) {
                    const float4* wrow = (const float4*)(W2 + (size_t)r * Dn);
                    float4 w0 = wrow[l8 * 4 + 0], w1 = wrow[l8 * 4 + 1];
                    float4 w2 = wrow[l8 * 4 + 2], w3 = wrow[l8 * 4 + 3];
                    p  = w0.x * h0.x + w0.y * h0.y + w0.z * h0.z + w0.w * h0.w;
                    p += w1.x * h1.x + w1.y * h1.y + w1.z * h1.z + w1.w * h1.w;
                    p += w2.x * h2.x + w2.y * h2.y + w2.z * h2.z + w2.w * h2.w;
                    p += w3.x * h3.x + w3.y * h3.y + w3.z * h3.z + w3.w * h3.w;
                }
                p += __shfl_xor_sync(0xffffffffu, p, 1);
                p += __shfl_xor_sync(0xffffffffu, p, 2);
                p += __shfl_xor_sync(0xffffffffu, p, 4);
                if (leader && r < row1) {
                    float l = p + b2[r];
                    if (l > M) { S = S * expf(M - l) + 1.0f; M = l; }
                    else       { S += expf(l - M); }
                    float v = l + gum[r];
                    unsigned long long k2 =
                        ((unsigned long long)ford(v) << 32) | (0xFFFFFFFFu - (unsigned)r);
                    if (k2 > key) key = k2;
                }
            }
            // merge within warp (non-leaders carry M=-inf, S=0, key=0)
#pragma unroll
            for (int o = 16; o; o >>= 1) {
                float M2 = __shfl_xor_sync(0xffffffffu, M, o);
                float S2 = __shfl_xor_sync(0xffffffffu, S, o);
                unsigned long long k2 = __shfl_xor_sync(0xffffffffu, key, o);
                lse_merge(M, S, M2, S2);
                if (k2 > key) key = k2;
            }
            if (lane == 0) { s_wM[wib] = M; s_wS[wib] = S; s_wK[wib] = key; }
            __syncthreads();
            if (wib == 0) {
                M = s_wM[lane]; S = s_wS[lane]; key = s_wK[lane];
#pragma unroll
                for (int o = 16; o; o >>= 1) {
                    float M2 = __shfl_xor_sync(0xffffffffu, M, o);
                    float S2 = __shfl_xor_sync(0xffffffffu, S, o);
                    unsigned long long k2 = __shfl_xor_sync(0xffffffffu, key, o);
                    lse_merge(M, S, M2, S2);
                    if (k2 > key) key = k2;
                }
                if (lane == 0) {
                    d_pM[b] = M; d_pS[b] = S;
                    atomicMax(&d_amax, key);
                }
            }
        }
        bar += NB; grid_sync(bar);

        // ---- phase C: merge partials + sample + next input (block 0) ----
        if (b == 0) {
            if (wib == 0) {
                float M = -INFINITY, S = 0.0f;
                for (int i = lane; i < NB; i += 32)
                    lse_merge(M, S, d_pM[i], d_pS[i]);
#pragma unroll
                for (int o = 16; o; o >>= 1) {
                    float M2 = __shfl_xor_sync(0xffffffffu, M, o);
                    float S2 = __shfl_xor_sync(0xffffffffu, S, o);
                    lse_merge(M, S, M2, S2);
                }
                if (lane == 0) {
                    unsigned long long key = d_amax;
                    d_amax = 0ull;
                    s_act = (int)(0xFFFFFFFFu - (unsigned)(key & 0xFFFFFFFFull));
                    s_cM = M; s_cS = S;
                }
            }
            __syncthreads();
            int act = s_act;
            s_red[t] = (t < Dn) ? s_hrelu[t] * W2[(size_t)act * Dn + t] : 0.0f;
            __syncthreads();
            for (int o = 64; o; o >>= 1) {
                if (t < o) s_red[t] += s_red[t + o];
                __syncthreads();
            }
            if (t == 0) {
                float logit = s_red[0] + b2[act];
                if (step < out_size) out[step] = (float)act;
                if (8 + step < out_size) out[8 + step] = logit - (s_cM + logf(s_cS));
            }
            if (t < Dn) s_inp[t] = emb[(size_t)act * Dn + t];
            __syncthreads();
        }
    }

    // ---- epilogue: final h, c (block 0) ----
    if (b == 0 && t < Dn) {
        if (16 + t < out_size) out[16 + t] = s_h[t];
        if (144 + t < out_size) out[144 + t] = s_c[t];
    }
}

// ---------------- host launcher ----------------
extern "C" void kernel_launch(void* const* d_in, const int* in_sizes, int n_in,
                              void* d_out, int out_size) {
    const float* state = (const float*)d_in[0];
    const float* model = (const float*)d_in[1];
    const int*   ei    = (const int*)d_in[2];
    const float* W_l   = (const float*)d_in[3];
    const float* W_r   = (const float*)d_in[4];
    const float* att   = (const float*)d_in[5];
    const float* cbias = (const float*)d_in[6];
    const float* Wih   = (const float*)d_in[7];
    const float* Whh   = (const float*)d_in[8];
    const float* bih   = (const float*)d_in[9];
    const float* bhh   = (const float*)d_in[10];
    const float* pW1   = (const float*)d_in[11];
    const float* pb1   = (const float*)d_in[12];
    const float* pW2   = (const float*)d_in[13];
    const float* pb2   = (const float*)d_in[14];
    const float* emb   = (const float*)d_in[15];
    float* out = (float*)d_out;

    float* xl_ptr = nullptr;
    float* xr_ptr = nullptr;
    cudaGetSymbolAddress((void**)&xl_ptr, d_xl);
    cudaGetSymbolAddress((void**)&xr_ptr, d_xr);

    setup_kernel<<<(HORn * NMn + 255) / 256, 256>>>();

    gemm_xwt<<<(NSn + 127) / 128, 256>>>(state, W_l, xl_ptr, NSn);
    gemm_xwt<<<(NMn + 127) / 128, 256>>>(model, W_r, xr_ptr, NMn);

    edge_score_exp<<<2048, 256>>>(ei, att);
    edge_w_kernel<<<(En + 255) / 256, 256>>>(ei);

    policy_kernel<<<NB, PTH>>>(cbias, Wih, Whh, bih, bhh,
                               pW1, pb1, pW2, pb2, emb, out, out_size);
}